// round 5
// baseline (speedup 1.0000x reference)
#include <cuda_runtime.h>
#include <math.h>
#include <stdint.h>

#define T 2048
#define D 768
#define NH 12
#define DH 64
#define D3 2304
#define D4 3072

#define BM 128
#define BN 128
#define BK 32

// ---------------- scratch (static device globals; no allocation) ----------------
__device__ float g_ln1[T * D];
__device__ float g_qkv[T * D3];
__device__ float g_w1[T * NH * 4];
__device__ float g_w2[T * NH * 4];
__device__ float g_r1[T * NH * 4];
__device__ float g_r2[T * NH * 4];
__device__ float g_jw[T * NH * 6];
__device__ float g_rd[T * NH * 6];
__device__ float g_gate[T];
__device__ float g_geov[T * D];
__device__ float g_pstd[T * D];
__device__ float g_pgeo[T * D];
__device__ float g_comb[T * D];
__device__ float g_res[T * D];
__device__ float g_m[T * D];
__device__ float g_fc[T * D4];

__device__ __forceinline__ float gelu_f(float v) {
    const float c = 0.7978845608028654f;
    float u = c * (v + 0.044715f * v * v * v);
    return 0.5f * v * (1.0f + tanhf(u));
}

__device__ __forceinline__ uint32_t f2tf32(float x) {
    uint32_t r;
    asm("cvt.rna.tf32.f32 %0, %1;" : "=r"(r) : "f"(x));
    return r;
}
__device__ __forceinline__ float tf32bits(float x) {
    return __uint_as_float(f2tf32(x));
}

__device__ __forceinline__ void mma_tf32(float c[4], const uint32_t a[4], const uint32_t b[2]) {
    asm volatile(
        "mma.sync.aligned.m16n8k8.row.col.f32.tf32.tf32.f32 "
        "{%0,%1,%2,%3},{%4,%5,%6,%7},{%8,%9},{%0,%1,%2,%3};"
        : "+f"(c[0]), "+f"(c[1]), "+f"(c[2]), "+f"(c[3])
        : "r"(a[0]), "r"(a[1]), "r"(a[2]), "r"(a[3]), "r"(b[0]), "r"(b[1]));
}

// ---------------- fused flash attention v2 ----------------
// 64 query rows per CTA (4 warps, 16 rows each), 64-key blocks.
// Q fragments live in registers; smem `buf` is reused: Q staging -> K tile -> P tile.
// KD: padded contraction width (multiple of 8); KLEN: real width.
template<int KD, int KLEN>
__global__ void flash2_k(const float* __restrict__ Qb, int qrs, int qhs,
                         const float* __restrict__ Kb, int krs, int khs,
                         const float* __restrict__ Vb, int vrs, int vhs,
                         const float* __restrict__ scaleArr, float cscale,
                         float* __restrict__ Ob)
{
    const int qb = blockIdx.x, h = blockIdx.y;
    const int q0 = qb * 64;
    const int tid = threadIdx.x, lane = tid & 31, w = tid >> 5;
    const int grp = lane >> 2, qid = lane & 3;
    const int wm = w * 16;

    __shared__ float buf[64][68];   // Q staging -> K tile -> P tile (tf32 bit patterns)
    __shared__ float Vs[64][68];    // V tile (tf32 bit patterns)

    const float scale = scaleArr ? scaleArr[h] : cscale;

    // stage Q (tf32 bits, zero-pad cols >= KLEN)
    for (int i = tid; i < 64 * KD; i += 128) {
        int r = i / KD, c = i % KD;
        float v = (c < KLEN) ? Qb[(size_t)(q0 + r) * qrs + h * qhs + c] : 0.f;
        buf[r][c] = tf32bits(v);
    }
    __syncthreads();

    // Q fragments to registers
    uint32_t qf[KD / 8][4];
#pragma unroll
    for (int s = 0; s < KD / 8; s++) {
        int ks = s * 8;
        qf[s][0] = __float_as_uint(buf[wm + grp][ks + qid]);
        qf[s][1] = __float_as_uint(buf[wm + grp + 8][ks + qid]);
        qf[s][2] = __float_as_uint(buf[wm + grp][ks + qid + 4]);
        qf[s][3] = __float_as_uint(buf[wm + grp + 8][ks + qid + 4]);
    }

    float m0 = -1e30f, m1 = -1e30f, l0 = 0.f, l1 = 0.f;
    float oacc[8][4] = {};
    const int rowg0 = q0 + wm + grp, rowg1 = rowg0 + 8;
    const int nkb = qb + 1;

    for (int kb = 0; kb < nkb; kb++) {
        const int s0 = kb * 64;
        __syncthreads();   // prior PV / Q-frag reads of buf complete
        for (int i = tid; i < 64 * KD; i += 128) {
            int r = i / KD, c = i % KD;
            float v = (c < KLEN) ? Kb[(size_t)(s0 + r) * krs + h * khs + c] : 0.f;
            buf[r][c] = tf32bits(v);
        }
        for (int i = tid; i < 64 * 64; i += 128) {
            int r = i >> 6, c = i & 63;
            Vs[r][c] = tf32bits(Vb[(size_t)(s0 + r) * vrs + h * vhs + c]);
        }
        __syncthreads();

        // ---- S = Q K^T (16 x 64 per warp) ----
        float sacc[8][4] = {};
#pragma unroll
        for (int s = 0; s < KD / 8; s++) {
            int ks = s * 8;
#pragma unroll
            for (int ni = 0; ni < 8; ni++) {
                uint32_t bf[2];
                bf[0] = __float_as_uint(buf[ni * 8 + grp][ks + qid]);
                bf[1] = __float_as_uint(buf[ni * 8 + grp][ks + qid + 4]);
                mma_tf32(sacc[ni], qf[s], bf);
            }
        }

        // ---- scale + causal mask (only diagonal block) ----
        const bool dMask = (kb == qb);
#pragma unroll
        for (int ni = 0; ni < 8; ni++)
#pragma unroll
            for (int e = 0; e < 4; e++) {
                float v = sacc[ni][e] * scale;
                if (dMask) {
                    int col = s0 + ni * 8 + qid * 2 + (e & 1);
                    int row = (e < 2) ? rowg0 : rowg1;
                    if (col > row) v = -1e30f;
                }
                sacc[ni][e] = v;
            }

        // ---- row max ----
        float tm0 = -1e30f, tm1 = -1e30f;
#pragma unroll
        for (int ni = 0; ni < 8; ni++) {
            tm0 = fmaxf(tm0, fmaxf(sacc[ni][0], sacc[ni][1]));
            tm1 = fmaxf(tm1, fmaxf(sacc[ni][2], sacc[ni][3]));
        }
        tm0 = fmaxf(tm0, __shfl_xor_sync(0xffffffff, tm0, 1));
        tm0 = fmaxf(tm0, __shfl_xor_sync(0xffffffff, tm0, 2));
        tm1 = fmaxf(tm1, __shfl_xor_sync(0xffffffff, tm1, 1));
        tm1 = fmaxf(tm1, __shfl_xor_sync(0xffffffff, tm1, 2));

        const float mn0 = fmaxf(m0, tm0), mn1 = fmaxf(m1, tm1);
        const float a0 = __expf(m0 - mn0), a1 = __expf(m1 - mn1);
        m0 = mn0; m1 = mn1;

        // ---- p = exp(s - m), row sums ----
        float rs0 = 0.f, rs1 = 0.f;
#pragma unroll
        for (int ni = 0; ni < 8; ni++) {
            float p0 = __expf(sacc[ni][0] - mn0);
            float p1 = __expf(sacc[ni][1] - mn0);
            float p2 = __expf(sacc[ni][2] - mn1);
            float p3 = __expf(sacc[ni][3] - mn1);
            sacc[ni][0] = p0; sacc[ni][1] = p1; sacc[ni][2] = p2; sacc[ni][3] = p3;
            rs0 += p0 + p1; rs1 += p2 + p3;
        }
        rs0 += __shfl_xor_sync(0xffffffff, rs0, 1);
        rs0 += __shfl_xor_sync(0xffffffff, rs0, 2);
        rs1 += __shfl_xor_sync(0xffffffff, rs1, 1);
        rs1 += __shfl_xor_sync(0xffffffff, rs1, 2);
        l0 = l0 * a0 + rs0;
        l1 = l1 * a1 + rs1;

        // ---- rescale O ----
#pragma unroll
        for (int ni = 0; ni < 8; ni++) {
            oacc[ni][0] *= a0; oacc[ni][1] *= a0;
            oacc[ni][2] *= a1; oacc[ni][3] *= a1;
        }

        // ---- all warps done with K -> reuse buf for P ----
        __syncthreads();
#pragma unroll
        for (int ni = 0; ni < 8; ni++) {
            int c = ni * 8 + qid * 2;
            buf[wm + grp][c]         = tf32bits(sacc[ni][0]);
            buf[wm + grp][c + 1]     = tf32bits(sacc[ni][1]);
            buf[wm + grp + 8][c]     = tf32bits(sacc[ni][2]);
            buf[wm + grp + 8][c + 1] = tf32bits(sacc[ni][3]);
        }
        __syncwarp();

        // ---- O += P V (P rows are warp-private) ----
#pragma unroll
        for (int ks = 0; ks < 64; ks += 8) {
            uint32_t af[4];
            af[0] = __float_as_uint(buf[wm + grp][ks + qid]);
            af[1] = __float_as_uint(buf[wm + grp + 8][ks + qid]);
            af[2] = __float_as_uint(buf[wm + grp][ks + qid + 4]);
            af[3] = __float_as_uint(buf[wm + grp + 8][ks + qid + 4]);
#pragma unroll
            for (int ni = 0; ni < 8; ni++) {
                uint32_t bf[2];
                bf[0] = __float_as_uint(Vs[ks + qid][ni * 8 + grp]);
                bf[1] = __float_as_uint(Vs[ks + qid + 4][ni * 8 + grp]);
                mma_tf32(oacc[ni], af, bf);
            }
        }
        __syncwarp();
    }

    // ---- normalize + write ----
    const float inv0 = 1.f / l0, inv1 = 1.f / l1;
#pragma unroll
    for (int ni = 0; ni < 8; ni++) {
        int c = ni * 8 + qid * 2;
        Ob[(size_t)rowg0 * D + h * DH + c]     = oacc[ni][0] * inv0;
        Ob[(size_t)rowg0 * D + h * DH + c + 1] = oacc[ni][1] * inv0;
        Ob[(size_t)rowg1 * D + h * DH + c]     = oacc[ni][2] * inv1;
        Ob[(size_t)rowg1 * D + h * DH + c + 1] = oacc[ni][3] * inv1;
    }
}

// ---------------- tf32 tensor-core GEMM (convert at staging) ----------------
__global__ void mma_gemm_k(const float* __restrict__ A, int lda, long long sA,
                           const float* __restrict__ B, int ldb, long long sB,
                           float* __restrict__ C, int ldc, long long sC,
                           const float* __restrict__ bias,
                           const float* __restrict__ resid, long long sR,
                           int M, int N, int K, int act)
{
    int z = blockIdx.z;
    A += (size_t)z * sA;
    B += (size_t)z * sB;
    C += (size_t)z * sC;
    if (resid) resid += (size_t)z * sR;

    const int bm0 = blockIdx.y * BM, bn0 = blockIdx.x * BN;

    __shared__ float As[BK][BM + 4];
    __shared__ float Bs[BK][BN + 4];

    const int tid = threadIdx.x, lane = tid & 31, wid = tid >> 5;
    const int wm = (wid & 3) * 32, wn = (wid >> 2) * 64;
    const int grp = lane >> 2, qid = lane & 3;

    float acc[2][8][4];
#pragma unroll
    for (int mi = 0; mi < 2; mi++)
#pragma unroll
        for (int ni = 0; ni < 8; ni++)
#pragma unroll
            for (int r = 0; r < 4; r++) acc[mi][ni][r] = 0.f;

    for (int k0 = 0; k0 < K; k0 += BK) {
#pragma unroll
        for (int i = tid; i < BM * BK / 4; i += 256) {
            int m = i >> 3, kq = i & 7, k = kq * 4;
            int ar = bm0 + m;
            float4 v = make_float4(0.f, 0.f, 0.f, 0.f);
            if (ar < M && k0 + k < K)
                v = *(const float4*)&A[(size_t)ar * lda + k0 + k];
            As[k][m]     = tf32bits(v.x);
            As[k + 1][m] = tf32bits(v.y);
            As[k + 2][m] = tf32bits(v.z);
            As[k + 3][m] = tf32bits(v.w);
        }
#pragma unroll
        for (int i = tid; i < BK * BN / 4; i += 256) {
            int k = i >> 5, nq = i & 31, n = nq * 4;
            int gn = bn0 + n, gk = k0 + k;
            float4 v = make_float4(0.f, 0.f, 0.f, 0.f);
            if (gk < K && gn < N)
                v = *(const float4*)&B[(size_t)gk * ldb + gn];
            Bs[k][n]     = tf32bits(v.x);
            Bs[k][n + 1] = tf32bits(v.y);
            Bs[k][n + 2] = tf32bits(v.z);
            Bs[k][n + 3] = tf32bits(v.w);
        }
        __syncthreads();
#pragma unroll
        for (int ks = 0; ks < BK; ks += 8) {
            uint32_t af[2][4], bf[8][2];
#pragma unroll
            for (int mi = 0; mi < 2; mi++) {
                int m0 = wm + mi * 16;
                af[mi][0] = __float_as_uint(As[ks + qid][m0 + grp]);
                af[mi][1] = __float_as_uint(As[ks + qid][m0 + grp + 8]);
                af[mi][2] = __float_as_uint(As[ks + qid + 4][m0 + grp]);
                af[mi][3] = __float_as_uint(As[ks + qid + 4][m0 + grp + 8]);
            }
#pragma unroll
            for (int ni = 0; ni < 8; ni++) {
                int n0 = wn + ni * 8;
                bf[ni][0] = __float_as_uint(Bs[ks + qid][n0 + grp]);
                bf[ni][1] = __float_as_uint(Bs[ks + qid + 4][n0 + grp]);
            }
#pragma unroll
            for (int mi = 0; mi < 2; mi++)
#pragma unroll
                for (int ni = 0; ni < 8; ni++)
                    mma_tf32(acc[mi][ni], af[mi], bf[ni]);
        }
        __syncthreads();
    }

#pragma unroll
    for (int mi = 0; mi < 2; mi++) {
#pragma unroll
        for (int ni = 0; ni < 8; ni++) {
            int colb = bn0 + wn + ni * 8 + qid * 2;
#pragma unroll
            for (int r = 0; r < 2; r++) {
                int row = bm0 + wm + mi * 16 + grp + r * 8;
                if (row >= M) continue;
#pragma unroll
                for (int cs = 0; cs < 2; cs++) {
                    int c = colb + cs;
                    if (c >= N) continue;
                    float v = acc[mi][ni][r * 2 + cs];
                    if (bias) v += bias[c];
                    if (act) v = gelu_f(v);
                    if (resid) v += resid[(size_t)row * ldc + c];
                    C[(size_t)row * ldc + c] = v;
                }
            }
        }
    }
}

// ---------------- fused 4x small projection (N=48) ----------------
__global__ void proj4_k(const float* __restrict__ ln1,
                        const float* __restrict__ w1w, const float* __restrict__ w2w,
                        const float* __restrict__ w1r, const float* __restrict__ w2r,
                        float* __restrict__ o1, float* __restrict__ o2,
                        float* __restrict__ o3, float* __restrict__ o4)
{
    int z = blockIdx.y;
    const float* W = (z == 0) ? w1w : (z == 1) ? w2w : (z == 2) ? w1r : w2r;
    float* O = (z == 0) ? o1 : (z == 1) ? o2 : (z == 2) ? o3 : o4;
    int shift = (z == 0) ? 1 : 0;
    int bm0 = blockIdx.x * 64;

    __shared__ float As[32][65];
    __shared__ float Ws[32][48];
    int tid = threadIdx.x;
    int tx = tid & 15, ty = tid >> 4;
    float acc[4][3] = {};

    for (int k0 = 0; k0 < D; k0 += 32) {
        for (int i = tid; i < 512; i += 256) {
            int m = i >> 3, kq = i & 7, k = kq * 4;
            int ar = bm0 + m - shift;
            float4 v = make_float4(0.f, 0.f, 0.f, 0.f);
            if (ar >= 0) v = *(const float4*)&ln1[(size_t)ar * D + k0 + k];
            As[k][m] = v.x; As[k + 1][m] = v.y; As[k + 2][m] = v.z; As[k + 3][m] = v.w;
        }
        for (int i = tid; i < 384; i += 256) {
            int k = i / 12, nq = i % 12, n = nq * 4;
            *(float4*)&Ws[k][n] = *(const float4*)&W[(size_t)(k0 + k) * 48 + n];
        }
        __syncthreads();
#pragma unroll
        for (int kk = 0; kk < 32; kk++) {
            float a[4], w2[3];
#pragma unroll
            for (int r = 0; r < 4; r++) a[r] = As[kk][ty * 4 + r];
#pragma unroll
            for (int c = 0; c < 3; c++) w2[c] = Ws[kk][tx * 3 + c];
#pragma unroll
            for (int r = 0; r < 4; r++)
#pragma unroll
                for (int c = 0; c < 3; c++) acc[r][c] += a[r] * w2[c];
        }
        __syncthreads();
    }
#pragma unroll
    for (int r = 0; r < 4; r++)
#pragma unroll
        for (int c = 0; c < 3; c++)
            O[(size_t)(bm0 + ty * 4 + r) * 48 + tx * 3 + c] = acc[r][c];
}

// ---------------- layernorm ----------------
__global__ void layernorm_k(const float* __restrict__ x, const float* __restrict__ g,
                            const float* __restrict__ b, float* __restrict__ y)
{
    int t = blockIdx.x;
    const float* row = x + (size_t)t * D;
    __shared__ float sh[256];
    int tid = threadIdx.x;
    float s = 0.f;
    for (int i = tid; i < D; i += 256) s += row[i];
    sh[tid] = s; __syncthreads();
    for (int st = 128; st > 0; st >>= 1) { if (tid < st) sh[tid] += sh[tid + st]; __syncthreads(); }
    float mean = sh[0] / D;
    __syncthreads();
    float v = 0.f;
    for (int i = tid; i < D; i += 256) { float d = row[i] - mean; v += d * d; }
    sh[tid] = v; __syncthreads();
    for (int st = 128; st > 0; st >>= 1) { if (tid < st) sh[tid] += sh[tid + st]; __syncthreads(); }
    float rstd = rsqrtf(sh[0] / D + 1e-5f);
    for (int i = tid; i < D; i += 256)
        y[(size_t)t * D + i] = (row[i] - mean) * rstd * g[i] + b[i];
}

// ---------------- Plucker exterior + J6 ----------------
__device__ __forceinline__ void exterior6(const float* a, const float* b, float* L)
{
    L[0] = a[0] * b[1] - a[1] * b[0];
    L[1] = a[0] * b[2] - a[2] * b[0];
    L[2] = a[0] * b[3] - a[3] * b[0];
    L[3] = a[1] * b[2] - a[2] * b[1];
    L[4] = a[1] * b[3] - a[3] * b[1];
    L[5] = a[2] * b[3] - a[3] * b[2];
    float n = sqrtf(L[0]*L[0] + L[1]*L[1] + L[2]*L[2] + L[3]*L[3] + L[4]*L[4] + L[5]*L[5]);
    float inv = 1.0f / fmaxf(n, 1e-12f);
#pragma unroll
    for (int i = 0; i < 6; i++) L[i] *= inv;
}

__global__ void lines_k(const float* __restrict__ w1, const float* __restrict__ w2,
                        const float* __restrict__ r1, const float* __restrict__ r2,
                        float* __restrict__ jw, float* __restrict__ rd)
{
    int idx = blockIdx.x * blockDim.x + threadIdx.x;
    if (idx >= T * NH) return;
    float L[6];
    exterior6(w1 + (size_t)idx * 4, w2 + (size_t)idx * 4, L);
    float* o = jw + (size_t)idx * 6;
    o[0] =  L[5]; o[1] = -L[4]; o[2] =  L[3];
    o[3] =  L[2]; o[4] = -L[1]; o[5] =  L[0];
    exterior6(r1 + (size_t)idx * 4, r2 + (size_t)idx * 4, L);
    float* p = rd + (size_t)idx * 6;
#pragma unroll
    for (int i = 0; i < 6; i++) p[i] = L[i];
}

// ---------------- gate ----------------
__global__ void gate_k(const float* __restrict__ ln1, const float* __restrict__ gw,
                       const float* __restrict__ gb, float* __restrict__ gate)
{
    int t = blockIdx.x;
    __shared__ float sh[128 * 12];
    int tid = threadIdx.x;
    float loc[12] = {};
    const float* row = ln1 + (size_t)t * D;
    for (int k = tid; k < D; k += 128) {
        float xv = row[k];
#pragma unroll
        for (int h = 0; h < 12; h++) loc[h] += xv * gw[k * 12 + h];
    }
#pragma unroll
    for (int h = 0; h < 12; h++) sh[tid * 12 + h] = loc[h];
    __syncthreads();
    for (int st = 64; st > 0; st >>= 1) {
        if (tid < st)
            for (int h = 0; h < 12; h++) sh[tid * 12 + h] += sh[(tid + st) * 12 + h];
        __syncthreads();
    }
    if (tid == 0) {
        float g = 0.f;
        for (int h = 0; h < 12; h++) g += 1.f / (1.f + expf(-(sh[h] + gb[h])));
        gate[t] = g / 12.f;
    }
}

// ---------------- combine gate ----------------
__global__ void combine_k(const float* __restrict__ so, const float* __restrict__ go,
                          const float* __restrict__ gate, float* __restrict__ out)
{
    int idx = blockIdx.x * 256 + threadIdx.x;
    if (idx >= T * D) return;
    float g = gate[idx / D];
    out[idx] = (1.f - g) * so[idx] + g * go[idx];
}

// ---------------- host launch ----------------
static float* symAddr(const void* sym)
{
    void* p = nullptr;
    cudaGetSymbolAddress(&p, sym);
    return (float*)p;
}

extern "C" void kernel_launch(void* const* d_in, const int* in_sizes, int n_in,
                              void* d_out, int out_size)
{
    const float* x       = (const float*)d_in[0];
    const float* ln1_g   = (const float*)d_in[1];
    const float* ln1_b   = (const float*)d_in[2];
    const float* qkv_w   = (const float*)d_in[3];
    const float* qkv_b   = (const float*)d_in[4];
    const float* w1w     = (const float*)d_in[5];
    const float* w2w     = (const float*)d_in[6];
    const float* w1r     = (const float*)d_in[7];
    const float* w2r     = (const float*)d_in[8];
    const float* geov_w  = (const float*)d_in[9];
    const float* geov_b  = (const float*)d_in[10];
    const float* gate_w  = (const float*)d_in[11];
    const float* gate_b  = (const float*)d_in[12];
    const float* inc     = (const float*)d_in[13];
    const float* out_w   = (const float*)d_in[14];
    const float* out_b   = (const float*)d_in[15];
    const float* ln2_g   = (const float*)d_in[16];
    const float* ln2_b   = (const float*)d_in[17];
    const float* fc_w    = (const float*)d_in[18];
    const float* fc_b    = (const float*)d_in[19];
    const float* proj_w  = (const float*)d_in[20];
    const float* proj_b  = (const float*)d_in[21];
    float* out = (float*)d_out;

    float* ln1   = symAddr(g_ln1);
    float* qkv   = symAddr(g_qkv);
    float* w1    = symAddr(g_w1);
    float* w2    = symAddr(g_w2);
    float* r1    = symAddr(g_r1);
    float* r2    = symAddr(g_r2);
    float* jw    = symAddr(g_jw);
    float* rd    = symAddr(g_rd);
    float* gate  = symAddr(g_gate);
    float* geov  = symAddr(g_geov);
    float* pstd  = symAddr(g_pstd);
    float* pgeo  = symAddr(g_pgeo);
    float* comb  = symAddr(g_comb);
    float* res   = symAddr(g_res);
    float* mbuf  = symAddr(g_m);
    float* fcb   = symAddr(g_fc);

    // 1. ln1
    layernorm_k<<<T, 256>>>(x, ln1_g, ln1_b, ln1);

    // 2. qkv = ln1 @ qkv_w + b
    mma_gemm_k<<<dim3(D3 / BN, T / BM, 1), 256>>>(ln1, D, 0, qkv_w, D3, 0, qkv, D3, 0,
                                                  qkv_b, nullptr, 0, T, D3, D, 0);

    // 3. fused small projections (N=48)
    proj4_k<<<dim3(T / 64, 4), 256>>>(ln1, w1w, w2w, w1r, w2r, w1, w2, r1, r2);

    // 4. exterior + J6
    lines_k<<<(T * NH + 255) / 256, 256>>>(w1, w2, r1, r2, jw, rd);

    // 5. gate
    gate_k<<<T, 128>>>(ln1, gate_w, gate_b, gate);

    // 6. geo_v
    mma_gemm_k<<<dim3(D / BN, T / BM, 1), 256>>>(ln1, D, 0, geov_w, D, 0, geov, D, 0,
                                                 geov_b, nullptr, 0, T, D, D, 0);

    // 7. std flash attention  (Q,K,V from qkv)
    flash2_k<64, 64><<<dim3(T / 64, NH), 128>>>(qkv, D3, DH, qkv + D, D3, DH,
                                                qkv + 2 * D, D3, DH,
                                                nullptr, 0.125f, pstd);

    // 8. geo flash attention  (read_lines . J_write, V = geov)
    flash2_k<8, 6><<<dim3(T / 64, NH), 128>>>(rd, NH * 6, 6, jw, NH * 6, 6,
                                              geov, D, DH,
                                              inc, 0.f, pgeo);

    // 9. combine
    combine_k<<<(T * D + 255) / 256, 256>>>(pstd, pgeo, gate, comb);

    // 10. out proj + residual
    mma_gemm_k<<<dim3(D / BN, T / BM, 1), 256>>>(comb, D, 0, out_w, D, 0, res, D, 0,
                                                 out_b, x, 0, T, D, D, 0);

    // 11. ln2
    layernorm_k<<<T, 256>>>(res, ln2_g, ln2_b, mbuf);

    // 12. fc + gelu
    mma_gemm_k<<<dim3(D4 / BN, T / BM, 1), 256>>>(mbuf, D, 0, fc_w, D4, 0, fcb, D4, 0,
                                                  fc_b, nullptr, 0, T, D4, D, 1);

    // 13. proj + bias + residual -> out
    mma_gemm_k<<<dim3(D / BN, T / BM, 1), 256>>>(fcb, D4, 0, proj_w, D, 0, out, D, 0,
                                                 proj_b, res, 0, T, D, D4, 0);
}

// round 6
// speedup vs baseline: 2.0728x; 2.0728x over previous
#include <cuda_runtime.h>
#include <math.h>
#include <stdint.h>

#define T 2048
#define D 768
#define NH 12
#define DH 64
#define D3 2304
#define D4 3072

// packed projection layout
#define NB     3276
#define C_QKV  0
#define C_GEOV 2304
#define C_W1   3072
#define C_W2   3120
#define C_R1   3168
#define C_R2   3216
#define C_GATE 3264

// ---------------- scratch (static device globals; no allocation) ----------------
__device__ float g_ln1[T * D];
__device__ float g_big[T * NB];
__device__ float g_bigw[D * NB];
__device__ float g_bigb[NB];
__device__ float g_jw[T * NH * 6];
__device__ float g_rd[T * NH * 6];
__device__ float g_gate[T];
__device__ float g_pstd[T * D];
__device__ float g_pgeo[T * D];
__device__ float g_comb[T * D];
__device__ float g_res[T * D];
__device__ float g_m[T * D];
__device__ float g_fc[T * D4];

__device__ __forceinline__ float gelu_f(float v) {
    const float c = 0.7978845608028654f;
    float u = c * (v + 0.044715f * v * v * v);
    return 0.5f * v * (1.0f + tanhf(u));
}

__device__ __forceinline__ uint32_t f2tf32(float x) {
    uint32_t r;
    asm("cvt.rna.tf32.f32 %0, %1;" : "=r"(r) : "f"(x));
    return r;
}
__device__ __forceinline__ float tf32bits(float x) {
    return __uint_as_float(f2tf32(x));
}

__device__ __forceinline__ void mma_tf32(float c[4], const uint32_t a[4], const uint32_t b[2]) {
    asm volatile(
        "mma.sync.aligned.m16n8k8.row.col.f32.tf32.tf32.f32 "
        "{%0,%1,%2,%3},{%4,%5,%6,%7},{%8,%9},{%0,%1,%2,%3};"
        : "+f"(c[0]), "+f"(c[1]), "+f"(c[2]), "+f"(c[3])
        : "r"(a[0]), "r"(a[1]), "r"(a[2]), "r"(a[3]), "r"(b[0]), "r"(b[1]));
}

__device__ __forceinline__ void cpa16(void* dst, const void* src, bool pred) {
    uint32_t d = (uint32_t)__cvta_generic_to_shared(dst);
    int sz = pred ? 16 : 0;
    asm volatile("cp.async.ca.shared.global [%0], [%1], 16, %2;"
                 :: "r"(d), "l"(src), "r"(sz));
}
#define CP_COMMIT() asm volatile("cp.async.commit_group;")
#define CP_WAIT1()  asm volatile("cp.async.wait_group 1;" ::: "memory")

// ---------------- pipelined tf32 GEMM, cp.async double-buffered ----------------
// CFG 0: 128x128 tile; CFG 1: 64x128 tile. 256 threads, BK=16, 2 stages.
template<int CFG>
__global__ void gemm_pl_k(const float* __restrict__ A, int lda,
                          const float* __restrict__ B, int ldb,
                          float* __restrict__ C, int ldc,
                          const float* __restrict__ bias,
                          const float* __restrict__ resid,
                          int M, int N, int K, int act)
{
    constexpr int BMt = CFG ? 64 : 128;
    constexpr int NI  = CFG ? 4 : 8;

    const int bm0 = blockIdx.y * BMt, bn0 = blockIdx.x * 128;

    __shared__ float As[2][BMt][20];     // row-major [m][k], pad 20
    __shared__ float Bs[2][16][132];     // [k][n], pad 132

    const int tid = threadIdx.x, lane = tid & 31, wid = tid >> 5;
    const int wm = CFG ? (wid & 1) * 32 : (wid & 3) * 32;
    const int wn = CFG ? (wid >> 1) * 32 : (wid >> 2) * 64;
    const int grp = lane >> 2, qid = lane & 3;

    float acc[2][NI][4];
#pragma unroll
    for (int mi = 0; mi < 2; mi++)
#pragma unroll
        for (int ni = 0; ni < NI; ni++)
#pragma unroll
            for (int r = 0; r < 4; r++) acc[mi][ni][r] = 0.f;

    auto prefetch = [&](int pb, int k0) {
#pragma unroll
        for (int i = tid; i < BMt * 4; i += 256) {
            int row = i >> 2, kq = i & 3;
            cpa16(&As[pb][row][kq * 4],
                  &A[(size_t)(bm0 + row) * lda + k0 + kq * 4], true);
        }
#pragma unroll
        for (int i = tid; i < 512; i += 256) {
            int k = i >> 5, nq = i & 31;
            int gn = bn0 + nq * 4;
            cpa16(&Bs[pb][k][nq * 4],
                  &B[(size_t)(k0 + k) * ldb + gn], gn < N);
        }
    };

    prefetch(0, 0);
    CP_COMMIT();
    int buf = 0;
    for (int k0 = 0; k0 < K; k0 += 16) {
        if (k0 + 16 < K) prefetch(buf ^ 1, k0 + 16);
        CP_COMMIT();
        CP_WAIT1();
        __syncthreads();
#pragma unroll
        for (int ks = 0; ks < 16; ks += 8) {
            uint32_t af[2][4];
#pragma unroll
            for (int mi = 0; mi < 2; mi++) {
                int m0 = wm + mi * 16;
                af[mi][0] = f2tf32(As[buf][m0 + grp][ks + qid]);
                af[mi][1] = f2tf32(As[buf][m0 + grp + 8][ks + qid]);
                af[mi][2] = f2tf32(As[buf][m0 + grp][ks + qid + 4]);
                af[mi][3] = f2tf32(As[buf][m0 + grp + 8][ks + qid + 4]);
            }
#pragma unroll
            for (int ni = 0; ni < NI; ni++) {
                int n0 = wn + ni * 8;
                uint32_t bf[2];
                bf[0] = f2tf32(Bs[buf][ks + qid][n0 + grp]);
                bf[1] = f2tf32(Bs[buf][ks + qid + 4][n0 + grp]);
#pragma unroll
                for (int mi = 0; mi < 2; mi++)
                    mma_tf32(acc[mi][ni], af[mi], bf);
            }
        }
        __syncthreads();
        buf ^= 1;
    }

#pragma unroll
    for (int mi = 0; mi < 2; mi++) {
#pragma unroll
        for (int ni = 0; ni < NI; ni++) {
            int colb = bn0 + wn + ni * 8 + qid * 2;
#pragma unroll
            for (int r = 0; r < 2; r++) {
                int row = bm0 + wm + mi * 16 + grp + r * 8;
#pragma unroll
                for (int cs = 0; cs < 2; cs++) {
                    int c = colb + cs;
                    if (c >= N) continue;
                    float v = acc[mi][ni][r * 2 + cs];
                    if (bias) v += bias[c];
                    if (act) v = gelu_f(v);
                    if (resid) v += resid[(size_t)row * ldc + c];
                    C[(size_t)row * ldc + c] = v;
                }
            }
        }
    }
}

// ---------------- weight/bias pack ----------------
__global__ void pack_k(const float* __restrict__ qkv_w, const float* __restrict__ geov_w,
                       const float* __restrict__ w1w, const float* __restrict__ w2w,
                       const float* __restrict__ w1r, const float* __restrict__ w2r,
                       const float* __restrict__ gate_w,
                       const float* __restrict__ qkv_b, const float* __restrict__ geov_b,
                       const float* __restrict__ gate_b,
                       float* __restrict__ bigw, float* __restrict__ bigb)
{
    int col = blockIdx.x * 256 + threadIdx.x;
    int k = blockIdx.y;
    if (col >= NB) return;
    float v;
    if      (col < C_GEOV) v = qkv_w[(size_t)k * D3 + col];
    else if (col < C_W1)   v = geov_w[(size_t)k * D + (col - C_GEOV)];
    else if (col < C_W2)   v = w1w[(size_t)k * 48 + (col - C_W1)];
    else if (col < C_R1)   v = w2w[(size_t)k * 48 + (col - C_W2)];
    else if (col < C_R2)   v = w1r[(size_t)k * 48 + (col - C_R1)];
    else if (col < C_GATE) v = w2r[(size_t)k * 48 + (col - C_R2)];
    else                   v = gate_w[(size_t)k * NH + (col - C_GATE)];
    bigw[(size_t)k * NB + col] = v;
    if (k == 0) {
        float b;
        if      (col < C_GEOV) b = qkv_b[col];
        else if (col < C_W1)   b = geov_b[col - C_GEOV];
        else if (col < C_GATE) b = 0.f;
        else                   b = gate_b[col - C_GATE];
        bigb[col] = b;
    }
}

// ---------------- fused flash attention (LPT order, reg Q, smem reuse) ----------------
template<int KD, int KLEN>
__global__ void flash2_k(const float* __restrict__ Qb, int qrs, int qhs,
                         const float* __restrict__ Kb, int krs, int khs,
                         const float* __restrict__ Vb, int vrs, int vhs,
                         const float* __restrict__ scaleArr, float cscale,
                         float* __restrict__ Ob)
{
    const int qb = gridDim.x - 1 - (int)blockIdx.x;   // heaviest CTAs first
    const int h = blockIdx.y;
    const int q0 = qb * 64;
    const int tid = threadIdx.x, lane = tid & 31, w = tid >> 5;
    const int grp = lane >> 2, qid = lane & 3;
    const int wm = w * 16;

    __shared__ float buf[64][68];   // Q staging -> K tile -> P tile (tf32 bits)
    __shared__ float Vs[64][68];    // V tile (tf32 bits)

    const float scale = scaleArr ? scaleArr[h] : cscale;

    // stage Q
    if (KD == 64) {
        for (int i = tid; i < 64 * 16; i += 128) {
            int r = i >> 4, c4 = (i & 15) * 4;
            float4 v = *(const float4*)&Qb[(size_t)(q0 + r) * qrs + h * qhs + c4];
            buf[r][c4]     = tf32bits(v.x);
            buf[r][c4 + 1] = tf32bits(v.y);
            buf[r][c4 + 2] = tf32bits(v.z);
            buf[r][c4 + 3] = tf32bits(v.w);
        }
    } else {
        for (int i = tid; i < 64 * KD; i += 128) {
            int r = i / KD, c = i % KD;
            float v = (c < KLEN) ? Qb[(size_t)(q0 + r) * qrs + h * qhs + c] : 0.f;
            buf[r][c] = tf32bits(v);
        }
    }
    __syncthreads();

    uint32_t qf[KD / 8][4];
#pragma unroll
    for (int s = 0; s < KD / 8; s++) {
        int ks = s * 8;
        qf[s][0] = __float_as_uint(buf[wm + grp][ks + qid]);
        qf[s][1] = __float_as_uint(buf[wm + grp + 8][ks + qid]);
        qf[s][2] = __float_as_uint(buf[wm + grp][ks + qid + 4]);
        qf[s][3] = __float_as_uint(buf[wm + grp + 8][ks + qid + 4]);
    }

    float m0 = -1e30f, m1 = -1e30f, l0 = 0.f, l1 = 0.f;
    float oacc[8][4] = {};
    const int rowg0 = q0 + wm + grp, rowg1 = rowg0 + 8;
    const int nkb = qb + 1;

    for (int kb = 0; kb < nkb; kb++) {
        const int s0 = kb * 64;
        __syncthreads();
        if (KD == 64) {
            for (int i = tid; i < 64 * 16; i += 128) {
                int r = i >> 4, c4 = (i & 15) * 4;
                float4 v = *(const float4*)&Kb[(size_t)(s0 + r) * krs + h * khs + c4];
                buf[r][c4]     = tf32bits(v.x);
                buf[r][c4 + 1] = tf32bits(v.y);
                buf[r][c4 + 2] = tf32bits(v.z);
                buf[r][c4 + 3] = tf32bits(v.w);
            }
        } else {
            for (int i = tid; i < 64 * KD; i += 128) {
                int r = i / KD, c = i % KD;
                float v = (c < KLEN) ? Kb[(size_t)(s0 + r) * krs + h * khs + c] : 0.f;
                buf[r][c] = tf32bits(v);
            }
        }
        for (int i = tid; i < 64 * 16; i += 128) {
            int r = i >> 4, c4 = (i & 15) * 4;
            float4 v = *(const float4*)&Vb[(size_t)(s0 + r) * vrs + h * vhs + c4];
            Vs[r][c4]     = tf32bits(v.x);
            Vs[r][c4 + 1] = tf32bits(v.y);
            Vs[r][c4 + 2] = tf32bits(v.z);
            Vs[r][c4 + 3] = tf32bits(v.w);
        }
        __syncthreads();

        // ---- S = Q K^T ----
        float sacc[8][4] = {};
#pragma unroll
        for (int s = 0; s < KD / 8; s++) {
            int ks = s * 8;
#pragma unroll
            for (int ni = 0; ni < 8; ni++) {
                uint32_t bf[2];
                bf[0] = __float_as_uint(buf[ni * 8 + grp][ks + qid]);
                bf[1] = __float_as_uint(buf[ni * 8 + grp][ks + qid + 4]);
                mma_tf32(sacc[ni], qf[s], bf);
            }
        }

        const bool dMask = (kb == nkb - 1);
#pragma unroll
        for (int ni = 0; ni < 8; ni++)
#pragma unroll
            for (int e = 0; e < 4; e++) {
                float v = sacc[ni][e] * scale;
                if (dMask) {
                    int col = s0 + ni * 8 + qid * 2 + (e & 1);
                    int row = (e < 2) ? rowg0 : rowg1;
                    if (col > row) v = -1e30f;
                }
                sacc[ni][e] = v;
            }

        float tm0 = -1e30f, tm1 = -1e30f;
#pragma unroll
        for (int ni = 0; ni < 8; ni++) {
            tm0 = fmaxf(tm0, fmaxf(sacc[ni][0], sacc[ni][1]));
            tm1 = fmaxf(tm1, fmaxf(sacc[ni][2], sacc[ni][3]));
        }
        tm0 = fmaxf(tm0, __shfl_xor_sync(0xffffffff, tm0, 1));
        tm0 = fmaxf(tm0, __shfl_xor_sync(0xffffffff, tm0, 2));
        tm1 = fmaxf(tm1, __shfl_xor_sync(0xffffffff, tm1, 1));
        tm1 = fmaxf(tm1, __shfl_xor_sync(0xffffffff, tm1, 2));

        const float mn0 = fmaxf(m0, tm0), mn1 = fmaxf(m1, tm1);
        const float a0 = __expf(m0 - mn0), a1 = __expf(m1 - mn1);
        m0 = mn0; m1 = mn1;

        float rs0 = 0.f, rs1 = 0.f;
#pragma unroll
        for (int ni = 0; ni < 8; ni++) {
            float p0 = __expf(sacc[ni][0] - mn0);
            float p1 = __expf(sacc[ni][1] - mn0);
            float p2 = __expf(sacc[ni][2] - mn1);
            float p3 = __expf(sacc[ni][3] - mn1);
            sacc[ni][0] = p0; sacc[ni][1] = p1; sacc[ni][2] = p2; sacc[ni][3] = p3;
            rs0 += p0 + p1; rs1 += p2 + p3;
        }
        rs0 += __shfl_xor_sync(0xffffffff, rs0, 1);
        rs0 += __shfl_xor_sync(0xffffffff, rs0, 2);
        rs1 += __shfl_xor_sync(0xffffffff, rs1, 1);
        rs1 += __shfl_xor_sync(0xffffffff, rs1, 2);
        l0 = l0 * a0 + rs0;
        l1 = l1 * a1 + rs1;

#pragma unroll
        for (int ni = 0; ni < 8; ni++) {
            oacc[ni][0] *= a0; oacc[ni][1] *= a0;
            oacc[ni][2] *= a1; oacc[ni][3] *= a1;
        }

        __syncthreads();   // all warps done reading K from buf
#pragma unroll
        for (int ni = 0; ni < 8; ni++) {
            int c = ni * 8 + qid * 2;
            buf[wm + grp][c]         = tf32bits(sacc[ni][0]);
            buf[wm + grp][c + 1]     = tf32bits(sacc[ni][1]);
            buf[wm + grp + 8][c]     = tf32bits(sacc[ni][2]);
            buf[wm + grp + 8][c + 1] = tf32bits(sacc[ni][3]);
        }
        __syncwarp();

#pragma unroll
        for (int ks = 0; ks < 64; ks += 8) {
            uint32_t af[4];
            af[0] = __float_as_uint(buf[wm + grp][ks + qid]);
            af[1] = __float_as_uint(buf[wm + grp + 8][ks + qid]);
            af[2] = __float_as_uint(buf[wm + grp][ks + qid + 4]);
            af[3] = __float_as_uint(buf[wm + grp + 8][ks + qid + 4]);
#pragma unroll
            for (int ni = 0; ni < 8; ni++) {
                uint32_t bf[2];
                bf[0] = __float_as_uint(Vs[ks + qid][ni * 8 + grp]);
                bf[1] = __float_as_uint(Vs[ks + qid + 4][ni * 8 + grp]);
                mma_tf32(oacc[ni], af, bf);
            }
        }
        __syncwarp();
    }

    const float inv0 = 1.f / l0, inv1 = 1.f / l1;
#pragma unroll
    for (int ni = 0; ni < 8; ni++) {
        int c = ni * 8 + qid * 2;
        Ob[(size_t)rowg0 * D + h * DH + c]     = oacc[ni][0] * inv0;
        Ob[(size_t)rowg0 * D + h * DH + c + 1] = oacc[ni][1] * inv0;
        Ob[(size_t)rowg1 * D + h * DH + c]     = oacc[ni][2] * inv1;
        Ob[(size_t)rowg1 * D + h * DH + c + 1] = oacc[ni][3] * inv1;
    }
}

// ---------------- layernorm ----------------
__global__ void layernorm_k(const float* __restrict__ x, const float* __restrict__ g,
                            const float* __restrict__ b, float* __restrict__ y)
{
    int t = blockIdx.x;
    const float* row = x + (size_t)t * D;
    __shared__ float sh[256];
    int tid = threadIdx.x;
    float s = 0.f;
    for (int i = tid; i < D; i += 256) s += row[i];
    sh[tid] = s; __syncthreads();
    for (int st = 128; st > 0; st >>= 1) { if (tid < st) sh[tid] += sh[tid + st]; __syncthreads(); }
    float mean = sh[0] / D;
    __syncthreads();
    float v = 0.f;
    for (int i = tid; i < D; i += 256) { float d = row[i] - mean; v += d * d; }
    sh[tid] = v; __syncthreads();
    for (int st = 128; st > 0; st >>= 1) { if (tid < st) sh[tid] += sh[tid + st]; __syncthreads(); }
    float rstd = rsqrtf(sh[0] / D + 1e-5f);
    for (int i = tid; i < D; i += 256)
        y[(size_t)t * D + i] = (row[i] - mean) * rstd * g[i] + b[i];
}

// ---------------- Plucker exterior + J6 (reads packed projections) ----------------
__device__ __forceinline__ void exterior6(const float* a, const float* b, float* L)
{
    L[0] = a[0] * b[1] - a[1] * b[0];
    L[1] = a[0] * b[2] - a[2] * b[0];
    L[2] = a[0] * b[3] - a[3] * b[0];
    L[3] = a[1] * b[2] - a[2] * b[1];
    L[4] = a[1] * b[3] - a[3] * b[1];
    L[5] = a[2] * b[3] - a[3] * b[2];
    float n = sqrtf(L[0]*L[0] + L[1]*L[1] + L[2]*L[2] + L[3]*L[3] + L[4]*L[4] + L[5]*L[5]);
    float inv = 1.0f / fmaxf(n, 1e-12f);
#pragma unroll
    for (int i = 0; i < 6; i++) L[i] *= inv;
}

__global__ void lines_k(const float* __restrict__ big,
                        float* __restrict__ jw, float* __restrict__ rd)
{
    int idx = blockIdx.x * blockDim.x + threadIdx.x;
    if (idx >= T * NH) return;
    int t = idx / NH, h = idx % NH;
    float a[4], b[4], L[6];
#pragma unroll
    for (int j = 0; j < 4; j++)
        a[j] = (t > 0) ? big[(size_t)(t - 1) * NB + C_W1 + h * 4 + j] : 0.f;
#pragma unroll
    for (int j = 0; j < 4; j++) b[j] = big[(size_t)t * NB + C_W2 + h * 4 + j];
    exterior6(a, b, L);
    float* o = jw + (size_t)idx * 6;
    o[0] =  L[5]; o[1] = -L[4]; o[2] =  L[3];
    o[3] =  L[2]; o[4] = -L[1]; o[5] =  L[0];
#pragma unroll
    for (int j = 0; j < 4; j++) a[j] = big[(size_t)t * NB + C_R1 + h * 4 + j];
#pragma unroll
    for (int j = 0; j < 4; j++) b[j] = big[(size_t)t * NB + C_R2 + h * 4 + j];
    exterior6(a, b, L);
    float* p = rd + (size_t)idx * 6;
#pragma unroll
    for (int i = 0; i < 6; i++) p[i] = L[i];
}

// ---------------- gate finish: sigmoid-mean of packed gate logits ----------------
__global__ void gate2_k(const float* __restrict__ big, float* __restrict__ gate)
{
    int t = blockIdx.x * 256 + threadIdx.x;
    if (t >= T) return;
    const float* row = big + (size_t)t * NB + C_GATE;
    float s = 0.f;
#pragma unroll
    for (int h = 0; h < NH; h++) s += 1.f / (1.f + __expf(-row[h]));
    gate[t] = s / NH;
}

// ---------------- combine gate ----------------
__global__ void combine_k(const float* __restrict__ so, const float* __restrict__ go,
                          const float* __restrict__ gate, float* __restrict__ out)
{
    int idx = blockIdx.x * 256 + threadIdx.x;
    if (idx >= T * D) return;
    float g = gate[idx / D];
    out[idx] = (1.f - g) * so[idx] + g * go[idx];
}

// ---------------- host launch ----------------
static float* symAddr(const void* sym)
{
    void* p = nullptr;
    cudaGetSymbolAddress(&p, sym);
    return (float*)p;
}

extern "C" void kernel_launch(void* const* d_in, const int* in_sizes, int n_in,
                              void* d_out, int out_size)
{
    const float* x       = (const float*)d_in[0];
    const float* ln1_g   = (const float*)d_in[1];
    const float* ln1_b   = (const float*)d_in[2];
    const float* qkv_w   = (const float*)d_in[3];
    const float* qkv_b   = (const float*)d_in[4];
    const float* w1w     = (const float*)d_in[5];
    const float* w2w     = (const float*)d_in[6];
    const float* w1r     = (const float*)d_in[7];
    const float* w2r     = (const float*)d_in[8];
    const float* geov_w  = (const float*)d_in[9];
    const float* geov_b  = (const float*)d_in[10];
    const float* gate_w  = (const float*)d_in[11];
    const float* gate_b  = (const float*)d_in[12];
    const float* inc     = (const float*)d_in[13];
    const float* out_w   = (const float*)d_in[14];
    const float* out_b   = (const float*)d_in[15];
    const float* ln2_g   = (const float*)d_in[16];
    const float* ln2_b   = (const float*)d_in[17];
    const float* fc_w    = (const float*)d_in[18];
    const float* fc_b    = (const float*)d_in[19];
    const float* proj_w  = (const float*)d_in[20];
    const float* proj_b  = (const float*)d_in[21];
    float* out = (float*)d_out;

    float* ln1   = symAddr(g_ln1);
    float* big   = symAddr(g_big);
    float* bigw  = symAddr(g_bigw);
    float* bigb  = symAddr(g_bigb);
    float* jw    = symAddr(g_jw);
    float* rd    = symAddr(g_rd);
    float* gate  = symAddr(g_gate);
    float* pstd  = symAddr(g_pstd);
    float* pgeo  = symAddr(g_pgeo);
    float* comb  = symAddr(g_comb);
    float* res   = symAddr(g_res);
    float* mbuf  = symAddr(g_m);
    float* fcb   = symAddr(g_fc);

    // 1. pack weights + biases (independent of ln1)
    pack_k<<<dim3((NB + 255) / 256, D), 256>>>(qkv_w, geov_w, w1w, w2w, w1r, w2r, gate_w,
                                               qkv_b, geov_b, gate_b, bigw, bigb);

    // 2. ln1
    layernorm_k<<<T, 256>>>(x, ln1_g, ln1_b, ln1);

    // 3. mega-GEMM: big = ln1 @ bigw + bigb   (qkv | geov | w1 w2 r1 r2 | gate)
    gemm_pl_k<0><<<dim3((NB + 127) / 128, T / 128), 256>>>(ln1, D, bigw, NB, big, NB,
                                                           bigb, nullptr, T, NB, D, 0);

    // 4. exterior + J6
    lines_k<<<(T * NH + 255) / 256, 256>>>(big, jw, rd);

    // 5. gate finish
    gate2_k<<<(T + 255) / 256, 256>>>(big, gate);

    // 6. std flash attention (Q,K,V slices of big)
    flash2_k<64, 64><<<dim3(T / 64, NH), 128>>>(big + C_QKV, NB, DH,
                                                big + C_QKV + D, NB, DH,
                                                big + C_QKV + 2 * D, NB, DH,
                                                nullptr, 0.125f, pstd);

    // 7. geo flash attention (read_lines . J_write, V = geov slice)
    flash2_k<8, 6><<<dim3(T / 64, NH), 128>>>(rd, NH * 6, 6, jw, NH * 6, 6,
                                              big + C_GEOV, NB, DH,
                                              inc, 0.f, pgeo);

    // 8. combine
    combine_k<<<(T * D + 255) / 256, 256>>>(pstd, pgeo, gate, comb);

    // 9. out proj + residual  (64x128 tiles -> 192 CTAs)
    gemm_pl_k<1><<<dim3(D / 128, T / 64), 256>>>(comb, D, out_w, D, res, D,
                                                 out_b, x, T, D, D, 0);

    // 10. ln2
    layernorm_k<<<T, 256>>>(res, ln2_g, ln2_b, mbuf);

    // 11. fc + gelu
    gemm_pl_k<0><<<dim3(D4 / 128, T / 128), 256>>>(mbuf, D, fc_w, D4, fcb, D4,
                                                   fc_b, nullptr, T, D4, D, 1);

    // 12. proj + bias + residual -> out
    gemm_pl_k<1><<<dim3(D / 128, T / 64), 256>>>(fcb, D4, proj_w, D, out, D,
                                                 proj_b, res, T, D, D4, 0);
}